// round 12
// baseline (speedup 1.0000x reference)
#include <cuda_runtime.h>
#include <math.h>

#define N_NODES 8192
#define F_IN 128
#define F_OUT 64
#define NEG_SLOPE 0.2f
#define VERY_SMALL 1000000000000.0f
#define SD_CHUNKS 256
#define ROWS_PER_CHUNK (N_NODES / SD_CHUNKS)   // 32 (4 per warp)

__device__ float g_s[N_NODES];
__device__ float g_d[N_NODES];
__device__ float g_bmax[SD_CHUNKS];
__device__ int g_done;   // sd chunks completed (zero-init, reset each launch)
__device__ int g_fin;    // CTAs finished (for end-of-launch reset)

__device__ __forceinline__ float block_reduce_sum(float v, float* red) {
    #pragma unroll
    for (int o = 16; o > 0; o >>= 1)
        v += __shfl_xor_sync(0xffffffffu, v, o);
    int warp = threadIdx.x >> 5;
    if ((threadIdx.x & 31) == 0) red[warp] = v;
    __syncthreads();
    if (warp == 0) {
        float x = (threadIdx.x < 8) ? red[threadIdx.x] : 0.f;
        #pragma unroll
        for (int o = 4; o > 0; o >>= 1)
            x += __shfl_xor_sync(0xffffffffu, x, o);
        if (threadIdx.x == 0) red[0] = x;
    }
    __syncthreads();
    return red[0];
}

// ONE fused kernel, grid 8192. CTAs 0..255 first compute a 32-row sd chunk
// (s[i]=h[i].ws, d[i]=h[i].wd, per-chunk d-max), then ALL CTAs spin-wait
// (idle, no memory traffic) until all chunks are published, then run the
// proven R7 softmax body on row blockIdx.x. No second launch, no PDL gap.
__global__ __launch_bounds__(256) void fused_kernel(const float* __restrict__ adj,
                                                    const float* __restrict__ h,
                                                    const float* __restrict__ w,
                                                    const float* __restrict__ a,
                                                    float* __restrict__ out) {
    __shared__ float red[8];
    __shared__ float sa[F_IN];
    __shared__ float sws[F_IN];
    __shared__ float swd[F_IN];
    const int i = blockIdx.x;
    const int t = threadIdx.x;
    const int warp = t >> 5;
    const int lane = t & 31;

    // ---------- Phase 1: sd chunk (CTAs 0..255 only, wave-1 resident) ----------
    if (i < SD_CHUNKS) {
        if (t < F_IN) sa[t] = a[t];
        __syncthreads();

        // ws[k] = w[k,:].a_src, wd[k] = w[k,:].a_dst, deterministically:
        // thread t at step r owns float4 f=t+256r of w (coalesced); the 16
        // threads sharing k=f>>4 are a 16-lane subgroup -> shfl sub-reduce.
        const float4* w4 = reinterpret_cast<const float4*>(w);
        const int j = (t & 15) * 4;
        #pragma unroll
        for (int r = 0; r < 8; ++r) {
            float4 v = w4[t + r * 256];
            float ps = v.x * sa[j] + v.y * sa[j + 1] + v.z * sa[j + 2] + v.w * sa[j + 3];
            float pd = v.x * sa[64 + j] + v.y * sa[64 + j + 1] + v.z * sa[64 + j + 2] + v.w * sa[64 + j + 3];
            #pragma unroll
            for (int o = 8; o > 0; o >>= 1) {
                ps += __shfl_xor_sync(0xffffffffu, ps, o);
                pd += __shfl_xor_sync(0xffffffffu, pd, o);
            }
            if ((t & 15) == 0) {
                int k = r * 16 + (t >> 4);
                sws[k] = ps;
                swd[k] = pd;
            }
        }
        __syncthreads();

        // 4 rows per warp: coalesced h loads, interleaved shfl chains.
        const int base = i * ROWS_PER_CHUNK + warp * 4;
        const float4 wsv = reinterpret_cast<const float4*>(sws)[lane];
        const float4 wdv = reinterpret_cast<const float4*>(swd)[lane];
        const float4* h4 = reinterpret_cast<const float4*>(h);

        float4 hv[4];
        #pragma unroll
        for (int r = 0; r < 4; ++r)
            hv[r] = h4[(size_t)(base + r) * (F_IN / 4) + lane];

        float s[4], d[4];
        #pragma unroll
        for (int r = 0; r < 4; ++r) {
            s[r] = hv[r].x * wsv.x + hv[r].y * wsv.y + hv[r].z * wsv.z + hv[r].w * wsv.w;
            d[r] = hv[r].x * wdv.x + hv[r].y * wdv.y + hv[r].z * wdv.z + hv[r].w * wdv.w;
        }
        #pragma unroll
        for (int o = 16; o > 0; o >>= 1) {
            #pragma unroll
            for (int r = 0; r < 4; ++r) {
                s[r] += __shfl_xor_sync(0xffffffffu, s[r], o);
                d[r] += __shfl_xor_sync(0xffffffffu, d[r], o);
            }
        }
        if (lane == 0) {
            float dmax = -INFINITY;
            #pragma unroll
            for (int r = 0; r < 4; ++r) {
                g_s[base + r] = s[r];
                g_d[base + r] = d[r];
                dmax = fmaxf(dmax, d[r]);
            }
            red[warp] = dmax;   // reuse red[] for warp maxima
        }
        __syncthreads();
        if (t == 0) {
            float m = red[0];
            #pragma unroll
            for (int k = 1; k < 8; ++k) m = fmaxf(m, red[k]);
            g_bmax[i] = m;
            __threadfence();                 // release g_s/g_d/g_bmax
            atomicAdd(&g_done, 1);
        }
        __syncthreads();                     // red[] free again
    }

    // ---------- Phase 2: wait for all sd chunks (idle spin, no traffic) ----------
    if (t == 0) {
        int v;
        do {
            asm volatile("ld.acquire.gpu.b32 %0, [%1];" : "=r"(v) : "l"(&g_done) : "memory");
        } while (v < SD_CHUNKS);
    }
    __syncthreads();   // block-wide propagation of the acquire

    // ---------- Phase 3: softmax row i (R7 body, unchanged) ----------
    const float si = g_s[i];

    // Warp-parallel D fold: 256 bmax = 64 float4, 2 per lane, 5 shfls.
    const float4* bm4 = reinterpret_cast<const float4*>(g_bmax);
    float4 m0 = __ldg(&bm4[lane]);
    float4 m1 = __ldg(&bm4[lane + 32]);
    float D = fmaxf(fmaxf(fmaxf(m0.x, m0.y), fmaxf(m0.z, m0.w)),
                    fmaxf(fmaxf(m1.x, m1.y), fmaxf(m1.z, m1.w)));
    #pragma unroll
    for (int o = 16; o > 0; o >>= 1)
        D = fmaxf(D, __shfl_xor_sync(0xffffffffu, D, o));
    float M = si + D;
    M = M >= 0.f ? M : NEG_SLOPE * M;

    const float4* ap = reinterpret_cast<const float4*>(adj + (size_t)i * N_NODES);
    const float4* dp = reinterpret_cast<const float4*>(g_d);

    float4 e[8];
    float lsum = 0.f;
    #pragma unroll
    for (int k = 0; k < 8; ++k) {
        const int c = t + k * 256;
        float4 av = __ldcs(&ap[c]);   // adj read once: evict-first
        float4 dv = __ldg(&dp[c]);    // 32 KB, reused by all CTAs: cached
        float v0 = si + dv.x; v0 = v0 >= 0.f ? v0 : NEG_SLOPE * v0; v0 = (av.x > 0.f) ? v0 : -VERY_SMALL;
        float v1 = si + dv.y; v1 = v1 >= 0.f ? v1 : NEG_SLOPE * v1; v1 = (av.y > 0.f) ? v1 : -VERY_SMALL;
        float v2 = si + dv.z; v2 = v2 >= 0.f ? v2 : NEG_SLOPE * v2; v2 = (av.z > 0.f) ? v2 : -VERY_SMALL;
        float v3 = si + dv.w; v3 = v3 >= 0.f ? v3 : NEG_SLOPE * v3; v3 = (av.w > 0.f) ? v3 : -VERY_SMALL;
        e[k].x = __expf(v0 - M);
        e[k].y = __expf(v1 - M);
        e[k].z = __expf(v2 - M);
        e[k].w = __expf(v3 - M);
        lsum += (e[k].x + e[k].y) + (e[k].z + e[k].w);
    }
    const float ssum = block_reduce_sum(lsum, red);
    const float inv = 1.0f / ssum;

    float4* op = reinterpret_cast<float4*>(out + (size_t)i * N_NODES);
    #pragma unroll
    for (int k = 0; k < 8; ++k) {
        const int c = t + k * 256;
        float4 o = e[k];
        o.x *= inv; o.y *= inv; o.z *= inv; o.w *= inv;
        __stcs(&op[c], o);   // out never re-read: streaming store
    }

    // ---------- Epilogue: last CTA resets counters for the next replay ----------
    if (t == 0) {
        int f = atomicAdd(&g_fin, 1);
        if (f == N_NODES - 1) {   // every other CTA already passed its spin
            g_done = 0;
            g_fin = 0;
        }
    }
}

extern "C" void kernel_launch(void* const* d_in, const int* in_sizes, int n_in,
                              void* d_out, int out_size) {
    const float* h   = (const float*)d_in[0];  // [8192,128]
    const float* adj = (const float*)d_in[1];  // [8192,8192]
    const float* w   = (const float*)d_in[2];  // [128,64]
    const float* a   = (const float*)d_in[3];  // [128,1]
    float* out = (float*)d_out;

    fused_kernel<<<N_NODES, 256>>>(adj, h, w, a, out);
}

// round 14
// speedup vs baseline: 1.0112x; 1.0112x over previous
#include <cuda_runtime.h>
#include <math.h>

#define N_NODES 8192
#define F_IN 128
#define F_OUT 64
#define NEG_SLOPE 0.2f
#define VERY_SMALL 1000000000000.0f
#define SD_CHUNKS 256
#define ROWS_PER_CHUNK (N_NODES / SD_CHUNKS)   // 32 (4 per warp)

__device__ float g_s[N_NODES];
__device__ float g_d[N_NODES];
__device__ float g_bmax[SD_CHUNKS];
__device__ int g_done;   // sd chunks completed (zero-init; reset each launch)
__device__ int g_fin;    // CTAs finished (drives the reset)

__device__ __forceinline__ float block_reduce_sum(float v, float* red) {
    #pragma unroll
    for (int o = 16; o > 0; o >>= 1)
        v += __shfl_xor_sync(0xffffffffu, v, o);
    int warp = threadIdx.x >> 5;
    if ((threadIdx.x & 31) == 0) red[warp] = v;
    __syncthreads();
    if (warp == 0) {
        float x = (threadIdx.x < 8) ? red[threadIdx.x] : 0.f;
        #pragma unroll
        for (int o = 4; o > 0; o >>= 1)
            x += __shfl_xor_sync(0xffffffffu, x, o);
        if (threadIdx.x == 0) red[0] = x;
    }
    __syncthreads();
    return red[0];
}

// ONE fused kernel, grid 8192. CTAs 0..255 compute a 32-row sd chunk and
// publish with threadfence+atomicAdd; all CTAs wait via ld.acquire.gpu
// (correct pairing — R13's nc-read bug fixed), then run the proven softmax
// body. KEY: sd outputs (g_s/g_d/g_bmax) are read via __ldcg (L2-only), so
// the acquire's L1 invalidation costs nothing (R12's perf bug fixed).
__global__ __launch_bounds__(256) void fused_kernel(const float* __restrict__ adj,
                                                    const float* __restrict__ h,
                                                    const float* __restrict__ w,
                                                    const float* __restrict__ a,
                                                    float* __restrict__ out) {
    __shared__ float red[8];
    __shared__ float sa[F_IN];
    __shared__ float sws[F_IN];
    __shared__ float swd[F_IN];
    const int i = blockIdx.x;
    const int t = threadIdx.x;
    const int warp = t >> 5;
    const int lane = t & 31;

    // ---------- Phase 1: sd chunk (CTAs 0..255, wave-1 resident) ----------
    if (i < SD_CHUNKS) {
        if (t < F_IN) sa[t] = a[t];
        __syncthreads();

        // ws[k]/wd[k]: thread t owns float4 f=t+256r of w (coalesced); the 16
        // threads sharing k=f>>4 shfl-subreduce deterministically.
        const float4* w4 = reinterpret_cast<const float4*>(w);
        const int j = (t & 15) * 4;
        #pragma unroll
        for (int r = 0; r < 8; ++r) {
            float4 v = w4[t + r * 256];
            float ps = v.x * sa[j] + v.y * sa[j + 1] + v.z * sa[j + 2] + v.w * sa[j + 3];
            float pd = v.x * sa[64 + j] + v.y * sa[64 + j + 1] + v.z * sa[64 + j + 2] + v.w * sa[64 + j + 3];
            #pragma unroll
            for (int o = 8; o > 0; o >>= 1) {
                ps += __shfl_xor_sync(0xffffffffu, ps, o);
                pd += __shfl_xor_sync(0xffffffffu, pd, o);
            }
            if ((t & 15) == 0) {
                int k = r * 16 + (t >> 4);
                sws[k] = ps;
                swd[k] = pd;
            }
        }
        __syncthreads();

        const int base = i * ROWS_PER_CHUNK + warp * 4;
        const float4 wsv = reinterpret_cast<const float4*>(sws)[lane];
        const float4 wdv = reinterpret_cast<const float4*>(swd)[lane];
        const float4* h4 = reinterpret_cast<const float4*>(h);

        float4 hv[4];
        #pragma unroll
        for (int r = 0; r < 4; ++r)
            hv[r] = h4[(size_t)(base + r) * (F_IN / 4) + lane];

        float s[4], d[4];
        #pragma unroll
        for (int r = 0; r < 4; ++r) {
            s[r] = hv[r].x * wsv.x + hv[r].y * wsv.y + hv[r].z * wsv.z + hv[r].w * wsv.w;
            d[r] = hv[r].x * wdv.x + hv[r].y * wdv.y + hv[r].z * wdv.z + hv[r].w * wdv.w;
        }
        #pragma unroll
        for (int o = 16; o > 0; o >>= 1) {
            #pragma unroll
            for (int r = 0; r < 4; ++r) {
                s[r] += __shfl_xor_sync(0xffffffffu, s[r], o);
                d[r] += __shfl_xor_sync(0xffffffffu, d[r], o);
            }
        }
        if (lane == 0) {
            float dmax = -INFINITY;
            #pragma unroll
            for (int r = 0; r < 4; ++r) {
                g_s[base + r] = s[r];
                g_d[base + r] = d[r];
                dmax = fmaxf(dmax, d[r]);
            }
            red[warp] = dmax;
        }
        __syncthreads();
        if (t == 0) {
            float m = red[0];
            #pragma unroll
            for (int k = 1; k < 8; ++k) m = fmaxf(m, red[k]);
            g_bmax[i] = m;
            __threadfence();                 // release: push g_s/g_d/g_bmax to L2
            atomicAdd(&g_done, 1);
        }
        __syncthreads();                     // red[] free again
    }

    // ---------- Phase 2: idle spin, PROPER acquire (pairs with the release) ----------
    if (t == 0) {
        int v;
        do {
            asm volatile("ld.acquire.gpu.b32 %0, [%1];" : "=r"(v) : "l"(&g_done) : "memory");
        } while (v < SD_CHUNKS);
    }
    __syncthreads();

    // ---------- Phase 3: softmax row i (R7 body; sd outputs via L2 .cg) ----------
    const float si = __ldcg(&g_s[i]);

    const float4* bm4 = reinterpret_cast<const float4*>(g_bmax);
    float4 m0 = __ldcg(&bm4[lane]);
    float4 m1 = __ldcg(&bm4[lane + 32]);
    float D = fmaxf(fmaxf(fmaxf(m0.x, m0.y), fmaxf(m0.z, m0.w)),
                    fmaxf(fmaxf(m1.x, m1.y), fmaxf(m1.z, m1.w)));
    #pragma unroll
    for (int o = 16; o > 0; o >>= 1)
        D = fmaxf(D, __shfl_xor_sync(0xffffffffu, D, o));
    float M = si + D;
    M = M >= 0.f ? M : NEG_SLOPE * M;

    const float4* ap = reinterpret_cast<const float4*>(adj + (size_t)i * N_NODES);
    const float4* dp = reinterpret_cast<const float4*>(g_d);

    float4 e[8];
    float lsum = 0.f;
    #pragma unroll
    for (int k = 0; k < 8; ++k) {
        const int c = t + k * 256;
        float4 av = __ldcs(&ap[c]);   // adj read once: evict-first
        float4 dv = __ldcg(&dp[c]);   // L2-only: coherent, L1-inval-immune
        float v0 = si + dv.x; v0 = v0 >= 0.f ? v0 : NEG_SLOPE * v0; v0 = (av.x > 0.f) ? v0 : -VERY_SMALL;
        float v1 = si + dv.y; v1 = v1 >= 0.f ? v1 : NEG_SLOPE * v1; v1 = (av.y > 0.f) ? v1 : -VERY_SMALL;
        float v2 = si + dv.z; v2 = v2 >= 0.f ? v2 : NEG_SLOPE * v2; v2 = (av.z > 0.f) ? v2 : -VERY_SMALL;
        float v3 = si + dv.w; v3 = v3 >= 0.f ? v3 : NEG_SLOPE * v3; v3 = (av.w > 0.f) ? v3 : -VERY_SMALL;
        e[k].x = __expf(v0 - M);
        e[k].y = __expf(v1 - M);
        e[k].z = __expf(v2 - M);
        e[k].w = __expf(v3 - M);
        lsum += (e[k].x + e[k].y) + (e[k].z + e[k].w);
    }
    const float ssum = block_reduce_sum(lsum, red);
    const float inv = 1.0f / ssum;

    float4* op = reinterpret_cast<float4*>(out + (size_t)i * N_NODES);
    #pragma unroll
    for (int k = 0; k < 8; ++k) {
        const int c = t + k * 256;
        float4 o = e[k];
        o.x *= inv; o.y *= inv; o.z *= inv; o.w *= inv;
        __stcs(&op[c], o);   // out never re-read: streaming store
    }

    // ---------- Epilogue: last CTA resets counters for the next graph replay ----------
    if (t == 0) {
        int f = atomicAdd(&g_fin, 1);
        if (f == N_NODES - 1) {   // every CTA has already passed its spin
            g_done = 0;
            g_fin = 0;
        }
    }
}

extern "C" void kernel_launch(void* const* d_in, const int* in_sizes, int n_in,
                              void* d_out, int out_size) {
    const float* h   = (const float*)d_in[0];  // [8192,128]
    const float* adj = (const float*)d_in[1];  // [8192,8192]
    const float* w   = (const float*)d_in[2];  // [128,64]
    const float* a   = (const float*)d_in[3];  // [128,1]
    float* out = (float*)d_out;

    fused_kernel<<<N_NODES, 256>>>(adj, h, w, a, out);
}

// round 15
// speedup vs baseline: 1.2049x; 1.1915x over previous
#include <cuda_runtime.h>
#include <math.h>

#define N_NODES 8192
#define F_IN 128
#define F_OUT 64
#define NEG_SLOPE 0.2f
#define VERY_SMALL 1000000000000.0f
#define SD_BLOCKS 256
#define ROWS_PER_SD_BLOCK (N_NODES / SD_BLOCKS)   // 32 (4 per warp)

__device__ float g_s[N_NODES];
__device__ float g_d[N_NODES];
__device__ float g_bmax[SD_BLOCKS];   // per-block max of d

// Kernel A: fused prep + sd + per-block d-max. 256 blocks x 256 thr, 32 rows.
// Signals PDL dependents immediately; they idle at their wait (no traffic).
__global__ __launch_bounds__(256) void sd_kernel(const float* __restrict__ h,
                                                 const float* __restrict__ w,
                                                 const float* __restrict__ a) {
    __shared__ float sa[F_IN];
    __shared__ float sws[F_IN];
    __shared__ float swd[F_IN];
    __shared__ float wmax[8];
    const int t = threadIdx.x;
    const int warp = t >> 5;
    const int lane = t & 31;

    // Dependent grid may start launching now; its CTAs block at wait
    // before issuing any memory traffic, so no interference (R11 lesson).
    asm volatile("griddepcontrol.launch_dependents;" ::: "memory");

    if (t < F_IN) sa[t] = a[t];
    __syncthreads();

    // ws[k]/wd[k]: thread t owns float4 f=t+256r of w (coalesced); the 16
    // threads sharing k=f>>4 shfl-subreduce deterministically.
    const float4* w4 = reinterpret_cast<const float4*>(w);
    const int j = (t & 15) * 4;
    #pragma unroll
    for (int r = 0; r < 8; ++r) {
        float4 v = w4[t + r * 256];
        float ps = v.x * sa[j] + v.y * sa[j + 1] + v.z * sa[j + 2] + v.w * sa[j + 3];
        float pd = v.x * sa[64 + j] + v.y * sa[64 + j + 1] + v.z * sa[64 + j + 2] + v.w * sa[64 + j + 3];
        #pragma unroll
        for (int o = 8; o > 0; o >>= 1) {
            ps += __shfl_xor_sync(0xffffffffu, ps, o);
            pd += __shfl_xor_sync(0xffffffffu, pd, o);
        }
        if ((t & 15) == 0) {
            int k = r * 16 + (t >> 4);
            sws[k] = ps;
            swd[k] = pd;
        }
    }
    __syncthreads();

    // 4 rows per warp, front-batched loads, interleaved shfl chains.
    const int base = blockIdx.x * ROWS_PER_SD_BLOCK + warp * 4;
    const float4 wsv = reinterpret_cast<const float4*>(sws)[lane];
    const float4 wdv = reinterpret_cast<const float4*>(swd)[lane];
    const float4* h4 = reinterpret_cast<const float4*>(h);

    float4 hv[4];
    #pragma unroll
    for (int r = 0; r < 4; ++r)
        hv[r] = h4[(size_t)(base + r) * (F_IN / 4) + lane];

    float s[4], d[4];
    #pragma unroll
    for (int r = 0; r < 4; ++r) {
        s[r] = hv[r].x * wsv.x + hv[r].y * wsv.y + hv[r].z * wsv.z + hv[r].w * wsv.w;
        d[r] = hv[r].x * wdv.x + hv[r].y * wdv.y + hv[r].z * wdv.z + hv[r].w * wdv.w;
    }
    #pragma unroll
    for (int o = 16; o > 0; o >>= 1) {
        #pragma unroll
        for (int r = 0; r < 4; ++r) {
            s[r] += __shfl_xor_sync(0xffffffffu, s[r], o);
            d[r] += __shfl_xor_sync(0xffffffffu, d[r], o);
        }
    }
    if (lane == 0) {
        float dmax = -INFINITY;
        #pragma unroll
        for (int r = 0; r < 4; ++r) {
            g_s[base + r] = s[r];
            g_d[base + r] = d[r];
            dmax = fmaxf(dmax, d[r]);
        }
        wmax[warp] = dmax;
    }
    __syncthreads();
    if (t == 0) {
        float m = wmax[0];
        #pragma unroll
        for (int k = 1; k < 8; ++k) m = fmaxf(m, wmax[k]);
        g_bmax[blockIdx.x] = m;
    }
}

__device__ __forceinline__ float block_reduce_sum(float v, float* red) {
    #pragma unroll
    for (int o = 16; o > 0; o >>= 1)
        v += __shfl_xor_sync(0xffffffffu, v, o);
    int warp = threadIdx.x >> 5;
    if ((threadIdx.x & 31) == 0) red[warp] = v;
    __syncthreads();
    if (warp == 0) {
        float x = (threadIdx.x < 8) ? red[threadIdx.x] : 0.f;
        #pragma unroll
        for (int o = 4; o > 0; o >>= 1)
            x += __shfl_xor_sync(0xffffffffu, x, o);
        if (threadIdx.x == 0) red[0] = x;
    }
    __syncthreads();
    return red[0];
}

// Kernel B: R7/R10 softmax body, wait at TOP (pre-launched CTAs idle until
// sd's writes are visible — no traffic interference with sd).
__global__ __launch_bounds__(256) void softmax_kernel(const float* __restrict__ adj,
                                                      float* __restrict__ out) {
    __shared__ float red[8];
    const int i = blockIdx.x;
    const int t = threadIdx.x;
    const int lane = t & 31;

    // PDL: block until sd_kernel's writes (g_s/g_d/g_bmax) are visible.
    asm volatile("griddepcontrol.wait;" ::: "memory");

    const float si = g_s[i];

    // Warp-parallel D fold: 256 bmax = 64 float4, 2 per lane, 5 shfls.
    const float4* bm4 = reinterpret_cast<const float4*>(g_bmax);
    float4 m0 = __ldg(&bm4[lane]);
    float4 m1 = __ldg(&bm4[lane + 32]);
    float D = fmaxf(fmaxf(fmaxf(m0.x, m0.y), fmaxf(m0.z, m0.w)),
                    fmaxf(fmaxf(m1.x, m1.y), fmaxf(m1.z, m1.w)));
    #pragma unroll
    for (int o = 16; o > 0; o >>= 1)
        D = fmaxf(D, __shfl_xor_sync(0xffffffffu, D, o));
    float M = si + D;
    M = M >= 0.f ? M : NEG_SLOPE * M;

    const float4* ap = reinterpret_cast<const float4*>(adj + (size_t)i * N_NODES);
    const float4* dp = reinterpret_cast<const float4*>(g_d);

    float4 e[8];
    float lsum = 0.f;
    #pragma unroll
    for (int k = 0; k < 8; ++k) {
        const int c = t + k * 256;
        float4 av = __ldcs(&ap[c]);   // adj read once: evict-first
        float4 dv = __ldg(&dp[c]);    // 32 KB, reused by all CTAs: L1-cached
        float v0 = si + dv.x; v0 = v0 >= 0.f ? v0 : NEG_SLOPE * v0; v0 = (av.x > 0.f) ? v0 : -VERY_SMALL;
        float v1 = si + dv.y; v1 = v1 >= 0.f ? v1 : NEG_SLOPE * v1; v1 = (av.y > 0.f) ? v1 : -VERY_SMALL;
        float v2 = si + dv.z; v2 = v2 >= 0.f ? v2 : NEG_SLOPE * v2; v2 = (av.z > 0.f) ? v2 : -VERY_SMALL;
        float v3 = si + dv.w; v3 = v3 >= 0.f ? v3 : NEG_SLOPE * v3; v3 = (av.w > 0.f) ? v3 : -VERY_SMALL;
        e[k].x = __expf(v0 - M);
        e[k].y = __expf(v1 - M);
        e[k].z = __expf(v2 - M);
        e[k].w = __expf(v3 - M);
        lsum += (e[k].x + e[k].y) + (e[k].z + e[k].w);
    }
    const float ssum = block_reduce_sum(lsum, red);
    const float inv = 1.0f / ssum;

    float4* op = reinterpret_cast<float4*>(out + (size_t)i * N_NODES);
    #pragma unroll
    for (int k = 0; k < 8; ++k) {
        const int c = t + k * 256;
        float4 o = e[k];
        o.x *= inv; o.y *= inv; o.z *= inv; o.w *= inv;
        __stcs(&op[c], o);   // out never re-read: streaming store
    }
}

extern "C" void kernel_launch(void* const* d_in, const int* in_sizes, int n_in,
                              void* d_out, int out_size) {
    const float* h   = (const float*)d_in[0];  // [8192,128]
    const float* adj = (const float*)d_in[1];  // [8192,8192]
    const float* w   = (const float*)d_in[2];  // [128,64]
    const float* a   = (const float*)d_in[3];  // [128,1]
    float* out = (float*)d_out;

    sd_kernel<<<SD_BLOCKS, 256>>>(h, w, a);

    // PDL: softmax CTAs pre-launch under sd_kernel; they idle at the wait
    // (issuing no traffic) until sd's results are visible.
    cudaLaunchConfig_t cfg = {};
    cfg.gridDim = dim3(N_NODES, 1, 1);
    cfg.blockDim = dim3(256, 1, 1);
    cfg.dynamicSmemBytes = 0;
    cudaLaunchAttribute attrs[1];
    attrs[0].id = cudaLaunchAttributeProgrammaticStreamSerialization;
    attrs[0].val.programmaticStreamSerializationAllowed = 1;
    cfg.attrs = attrs;
    cfg.numAttrs = 1;
    cudaLaunchKernelEx(&cfg, softmax_kernel, adj, out);
}